// round 9
// baseline (speedup 1.0000x reference)
#include <cuda_runtime.h>
#include <cuda_bf16.h>
#include <cstdint>

#define L_HOPS 5
#define D_DIM  32
#define E_CAP  131072          // capacity; actual E passed at runtime (E <= E_CAP)

// SoA table: plane l holds dots[l][e] = <edge_vector[l], edge_attr[e]>.
// 5 x 512 KB = 2.6 MB, L2-resident. SoA => coalesced writes in precompute.
__device__ float g_t0[E_CAP];
__device__ float g_t1[E_CAP];
__device__ float g_t2[E_CAP];
__device__ float g_t3[E_CAP];
__device__ float g_t4[E_CAP];

// 1/max(len,1); len==0 -> 0 (sum is 0 anyway)
__constant__ float c_inv[8] = {0.0f, 1.0f, 0.5f, 1.0f / 3.0f, 0.25f, 0.2f, 0.0f, 0.0f};

// ---------------------------------------------------------------------------
// Kernel 1: per-(edge, hop) dot products. One thread per edge (128 B row).
// SoA writes: each of the 5 stores is fully coalesced across the warp.
// ---------------------------------------------------------------------------
__global__ void __launch_bounds__(256) precompute_dots_kernel(
    const float* __restrict__ edge_attr,   // [E, 32]
    const float* __restrict__ edge_vector, // [5, 32]
    int E)
{
    __shared__ float sev[L_HOPS * D_DIM];
    if (threadIdx.x < L_HOPS * D_DIM)
        sev[threadIdx.x] = edge_vector[threadIdx.x];
    __syncthreads();

    int e = blockIdx.x * blockDim.x + threadIdx.x;
    if (e >= E) return;

    const float4* row = reinterpret_cast<const float4*>(edge_attr + (size_t)e * D_DIM);

    float acc0 = 0.f, acc1 = 0.f, acc2 = 0.f, acc3 = 0.f, acc4 = 0.f;
#pragma unroll
    for (int i = 0; i < D_DIM / 4; i++) {
        float4 v = row[i];
#pragma unroll
        for (int c = 0; c < 4; c++) {
            float a = (c == 0) ? v.x : (c == 1) ? v.y : (c == 2) ? v.z : v.w;
            int d = i * 4 + c;
            acc0 = fmaf(a, sev[0 * D_DIM + d], acc0);
            acc1 = fmaf(a, sev[1 * D_DIM + d], acc1);
            acc2 = fmaf(a, sev[2 * D_DIM + d], acc2);
            acc3 = fmaf(a, sev[3 * D_DIM + d], acc3);
            acc4 = fmaf(a, sev[4 * D_DIM + d], acc4);
        }
    }

    g_t0[e] = acc0;
    g_t1[e] = acc1;
    g_t2[e] = acc2;
    g_t3[e] = acc3;
    g_t4[e] = acc4;
}

// ---------------------------------------------------------------------------
// Kernel 2: 4 pairs per thread (best measured variant), SoA gathers.
// ---------------------------------------------------------------------------
__global__ void __launch_bounds__(256) pair_reduce_kernel4(
    const int* __restrict__ path_edges,  // [P, 5]
    const int* __restrict__ path_len,    // [P]
    float* __restrict__ out,             // [P]
    int Pq)                              // P / 4
{
    int t = blockIdx.x * blockDim.x + threadIdx.x;
    if (t >= Pq) return;

    // 4 pairs: 20 indices = 5 x int4 (80 B, 16B-aligned), lens = 1 x int4.
    const int4* pe = reinterpret_cast<const int4*>(path_edges) + (size_t)t * 5;
    int4 a  = __ldg(pe + 0);
    int4 b  = __ldg(pe + 1);
    int4 c  = __ldg(pe + 2);
    int4 d  = __ldg(pe + 3);
    int4 e4 = __ldg(pe + 4);
    int4 ln = __ldg(reinterpret_cast<const int4*>(path_len) + t);

    // Predicated SoA gathers (all independent; compiler batches them).
    float v00 = (ln.x > 0) ? __ldg(&g_t0[a.x])  : 0.f;
    float v01 = (ln.x > 1) ? __ldg(&g_t1[a.y])  : 0.f;
    float v02 = (ln.x > 2) ? __ldg(&g_t2[a.z])  : 0.f;
    float v03 = (ln.x > 3) ? __ldg(&g_t3[a.w])  : 0.f;
    float v04 = (ln.x > 4) ? __ldg(&g_t4[b.x])  : 0.f;

    float v10 = (ln.y > 0) ? __ldg(&g_t0[b.y])  : 0.f;
    float v11 = (ln.y > 1) ? __ldg(&g_t1[b.z])  : 0.f;
    float v12 = (ln.y > 2) ? __ldg(&g_t2[b.w])  : 0.f;
    float v13 = (ln.y > 3) ? __ldg(&g_t3[c.x])  : 0.f;
    float v14 = (ln.y > 4) ? __ldg(&g_t4[c.y])  : 0.f;

    float v20 = (ln.z > 0) ? __ldg(&g_t0[c.z])  : 0.f;
    float v21 = (ln.z > 1) ? __ldg(&g_t1[c.w])  : 0.f;
    float v22 = (ln.z > 2) ? __ldg(&g_t2[d.x])  : 0.f;
    float v23 = (ln.z > 3) ? __ldg(&g_t3[d.y])  : 0.f;
    float v24 = (ln.z > 4) ? __ldg(&g_t4[d.z])  : 0.f;

    float v30 = (ln.w > 0) ? __ldg(&g_t0[d.w])  : 0.f;
    float v31 = (ln.w > 1) ? __ldg(&g_t1[e4.x]) : 0.f;
    float v32 = (ln.w > 2) ? __ldg(&g_t2[e4.y]) : 0.f;
    float v33 = (ln.w > 3) ? __ldg(&g_t3[e4.z]) : 0.f;
    float v34 = (ln.w > 4) ? __ldg(&g_t4[e4.w]) : 0.f;

    float4 r;
    r.x = (((v00 + v01) + (v02 + v03)) + v04) * c_inv[ln.x & 7];
    r.y = (((v10 + v11) + (v12 + v13)) + v14) * c_inv[ln.y & 7];
    r.z = (((v20 + v21) + (v22 + v23)) + v24) * c_inv[ln.z & 7];
    r.w = (((v30 + v31) + (v32 + v33)) + v34) * c_inv[ln.w & 7];
    reinterpret_cast<float4*>(out)[t] = r;
}

// Scalar fallback for P not divisible by 4 (not hit for N=1024).
__global__ void pair_reduce_tail(
    const int* __restrict__ path_edges,
    const int* __restrict__ path_len,
    float* __restrict__ out,
    int start, int P)
{
    int p = start + blockIdx.x * blockDim.x + threadIdx.x;
    if (p >= P) return;
    int len = path_len[p];
    const int* row = path_edges + (size_t)p * L_HOPS;
    float s = 0.f;
    s += (len > 0) ? __ldg(&g_t0[row[0]]) : 0.f;
    s += (len > 1) ? __ldg(&g_t1[row[1]]) : 0.f;
    s += (len > 2) ? __ldg(&g_t2[row[2]]) : 0.f;
    s += (len > 3) ? __ldg(&g_t3[row[3]]) : 0.f;
    s += (len > 4) ? __ldg(&g_t4[row[4]]) : 0.f;
    out[p] = s * c_inv[len & 7];
}

// ---------------------------------------------------------------------------
// Inputs: x[N,32], edge_attr[E,32], edge_vector[5,32],
//         path_edges[P,5] (int32), path_len[P] (int32)  -> out float32 [P]
// ---------------------------------------------------------------------------
extern "C" void kernel_launch(void* const* d_in, const int* in_sizes, int n_in,
                              void* d_out, int out_size)
{
    const float* edge_attr   = (const float*)d_in[1];
    const float* edge_vector = (const float*)d_in[2];
    const int*   path_edges  = (const int*)d_in[3];
    const int*   path_len    = (const int*)d_in[4];
    float*       out         = (float*)d_out;

    int E = in_sizes[1] / D_DIM;
    int P = out_size;

    {
        int threads = 256;
        int blocks = (E + threads - 1) / threads;
        precompute_dots_kernel<<<blocks, threads>>>(edge_attr, edge_vector, E);
    }
    int Pq = P / 4;
    if (Pq > 0) {
        int threads = 256;
        int blocks = (Pq + threads - 1) / threads;
        pair_reduce_kernel4<<<blocks, threads>>>(path_edges, path_len, out, Pq);
    }
    int done = Pq * 4;
    if (done < P) {
        int rem = P - done;
        pair_reduce_tail<<<(rem + 255) / 256, 256>>>(path_edges, path_len, out, done, P);
    }
}